// round 17
// baseline (speedup 1.0000x reference)
#include <cuda_runtime.h>
#include <cuda_fp16.h>
#include <math.h>

#define H 192
#define W 192
#define HW (H*W)
#define NCH 24          // BT*C = 8*3
#define CROP 174
#define H0 9
#define W0 9
#define NPIX (CROP*CROP)        // 30276
#define EXT 178                 // CROP + 2*2 halo
#define NPIXE (EXT*EXT)         // 31684
#define NCAND 75
#define SPLIT2 39               // B: 15*39 = 585 blocks (single wave @ occ 4)
#define NSPLITA 160             // A: 3*160 = 480 warp blocks
#define NBT 8
#define NLANES 64
#define NTHR 192
#define REF_PX 384                           // ref pixels per block
#define REF_CHUNKS ((NPIX + REF_PX - 1) / REF_PX)  // 79
#define REF_BLKS (3 * REF_CHUNKS)            // 237

// Ref: [g][p][8ch]; W: [rot][g][pext][8ch]
__device__ __half g_refT[NPIX * NCH];
__device__ __half g_W[3 * 3 * NPIXE * 8];
__device__ float  g_partial[NCAND * SPLIT2 * NBT];
__device__ int    g_count;

// ---------------------------------------------------------------------------
// Kernel 1 (prep): blocks [0, 480): bilinear warp for 3 rotations on the
// 178x178 extended grid, sampling the fp32 image DIRECTLY (coalesced 128B
// per-channel warp loads), fp32 bilinear, single rounding to half.
// Blocks [480, 717): ref-crop fp32 -> half conversion (384 px per block).
// ---------------------------------------------------------------------------
__global__ __launch_bounds__(NTHR) void prep_kernel(const float* __restrict__ img,
                                                    const float* __restrict__ ref) {
    const int b = blockIdx.x;
    const int t = threadIdx.x;
    if (b == 0 && t == 0) g_count = 0;

    if (b < 3 * NSPLITA) {
        const int rot = b / NSPLITA;
        const int sA  = b - rot * NSPLITA;
        const int warp = t >> 5;
        const int lane = t & 31;
        const int g = warp % 3;
        const int lane_px = (warp / 3) * 32 + lane;

        const float arot = -(float)(rot - 1) * (float)(M_PI / 180.0);
        const float cr = cosf(arot);
        const float sr = sinf(arot);

        const float SC = 96.0f / 95.5f;
        const float u0 = -86.5f;
        const float v0 = -86.5f;
        const float ax = SC * cr;
        const float bx = -SC * sr;
        const float ay = SC * sr;
        const float by = SC * cr;
        const float cx0e = SC * (cr * u0 - sr * v0) + 95.5f - 2.0f * (ax + bx);
        const float cy0e = SC * (sr * u0 + cr * v0) + 95.5f - 2.0f * (ay + by);

        const int chunkA = (NPIXE + NSPLITA - 1) / NSPLITA;
        const int pb = sA * chunkA;
        const int pe = min(pb + chunkA, NPIXE);

        int p = pb + lane_px;
        int pj;
        float xv, yv;
        {
            const int pi0 = p / EXT;
            pj = p - pi0 * EXT;
            xv = fmaf(ax, (float)pj, fmaf(bx, (float)pi0, cx0e));
            yv = fmaf(ay, (float)pj, fmaf(by, (float)pi0, cy0e));
        }
        const float dxn = ax * (float)NLANES;
        const float dxw = ax * (float)(NLANES - EXT) + bx;
        const float dyn = ay * (float)NLANES;
        const float dyw = ay * (float)(NLANES - EXT) + by;
        const float* imgG = img + (g * 8) * HW;   // first channel of this group
        int woff = ((rot * 3 + g) * NPIXE + p) * 8;

        #pragma unroll 2
        for (; p < pe; p += NLANES) {
            const float x0f = floorf(xv);
            const float y0f = floorf(yv);
            const float wx = xv - x0f;
            const float wy = yv - y0f;
            const int x0 = (int)x0f;
            const int y0 = (int)y0f;

            const float wx1 = 1.0f - wx;
            const float wy1 = 1.0f - wy;
            const float wA = wx1 * wy1;
            const float wB = wx  * wy1;
            const float wC = wx1 * wy;
            const float wD = wx  * wy;

            const float* p0 = imgG + y0 * W + x0;

            float4 o;
            __half2* ho = (__half2*)&o;
            #pragma unroll
            for (int c2 = 0; c2 < 4; c2++) {
                const float* pc = p0 + (2 * c2) * HW;
                const float* pd = pc + HW;
                float va0 = pc[0], vb0 = pc[1], vc0 = pc[W], vd0 = pc[W + 1];
                float va1 = pd[0], vb1 = pd[1], vc1 = pd[W], vd1 = pd[W + 1];
                float v0 = wA * va0;
                v0 = fmaf(wB, vb0, v0);
                v0 = fmaf(wC, vc0, v0);
                v0 = fmaf(wD, vd0, v0);
                float v1 = wA * va1;
                v1 = fmaf(wB, vb1, v1);
                v1 = fmaf(wC, vc1, v1);
                v1 = fmaf(wD, vd1, v1);
                ho[c2] = __floats2half2_rn(v0, v1);
            }
            *(float4*)(g_W + woff) = o;

            pj += NLANES;
            const bool wrap = (pj >= EXT);
            pj = wrap ? pj - EXT : pj;
            xv += wrap ? dxw : dxn;
            yv += wrap ? dyw : dyn;
            woff += NLANES * 8;
        }
    } else {
        // Ref-crop conversion: 384 px per block (2 px/thread), one ch-group.
        __shared__ __half s[REF_PX][10];
        const int bb = b - 3 * NSPLITA;
        const int g = bb / REF_CHUNKS;
        const int c = bb - g * REF_CHUNKS;
        const int p0 = c * REF_PX;
        #pragma unroll
        for (int rep = 0; rep < 2; rep++) {
            const int lp = rep * NTHR + t;
            const int p  = p0 + lp;
            const bool valid = (p < NPIX);
            const int i = p / CROP;
            const int j = p - i * CROP;
            const int src = (i + H0) * W + (j + W0);
            #pragma unroll
            for (int ch = 0; ch < 8; ch++)
                s[lp][ch] = valid ? __float2half(ref[(g * 8 + ch) * HW + src]) : __half(0.0f);
        }
        __syncthreads();
        unsigned int* out32 = (unsigned int*)g_refT;
        #pragma unroll
        for (int w = 0; w < 8; w++) {
            const int idx = w * NTHR + t;     // 0..1535
            const int px = idx >> 2;
            const int q  = idx & 3;
            if (p0 + px < NPIX)
                out32[(g * NPIX + p0 + px) * 4 + q] = *(const unsigned int*)&s[px][2 * q];
        }
    }
}

// ---------------------------------------------------------------------------
// Kernel B: SAD with 5-way j-shift sharing, half2 accumulation over the
// whole chunk (<=13 iters/lane); half2 -> fp32 at the smem write. occ 4.
// ---------------------------------------------------------------------------
__global__ __launch_bounds__(NTHR, 4) void sad_kernel(float* __restrict__ out,
                                                      int out_size) {
    const int pair = blockIdx.x;     // 0..14
    const int s = blockIdx.y;        // 0..SPLIT2-1
    const int t = threadIdx.x;
    const int warp = t >> 5;
    const int lane = t & 31;
    const int g = warp % 3;
    const int lane_px = (warp / 3) * 32 + lane;

    const int i0 = pair / 3;
    const int i2 = pair - 3 * i0;

    __half2 ah[5][4];
    #pragma unroll
    for (int a = 0; a < 5; a++)
        #pragma unroll
        for (int u = 0; u < 4; u++) ah[a][u] = __float2half2_rn(0.0f);

    const int chunk = (NPIX + SPLIT2 - 1) / SPLIT2;
    const int p_begin = s * chunk;
    const int p_end   = min(p_begin + chunk, NPIX);

    int p = p_begin + lane_px;
    int pj;
    int wbase;
    {
        const int pi0 = p / CROP;
        pj = p - pi0 * CROP;
        wbase = ((i2 * 3 + g) * NPIXE + (pi0 + 4 - i0) * EXT + pj) * 8;
    }
    int refoff = (g * NPIX + p) * 8;

    #pragma unroll 2
    for (; p < p_end; p += NLANES) {
        const float4 fR  = *(const float4*)(g_refT + refoff);
        const float4 fW0 = *(const float4*)(g_W + wbase);        // i1 = 4
        const float4 fW1 = *(const float4*)(g_W + wbase + 8);    // i1 = 3
        const float4 fW2 = *(const float4*)(g_W + wbase + 16);   // i1 = 2
        const float4 fW3 = *(const float4*)(g_W + wbase + 24);   // i1 = 1
        const float4 fW4 = *(const float4*)(g_W + wbase + 32);   // i1 = 0
        const __half2* hR = (const __half2*)&fR;

        const __half2* hW0 = (const __half2*)&fW0;
        const __half2* hW1 = (const __half2*)&fW1;
        const __half2* hW2 = (const __half2*)&fW2;
        const __half2* hW3 = (const __half2*)&fW3;
        const __half2* hW4 = (const __half2*)&fW4;

        #pragma unroll
        for (int u = 0; u < 4; u++) {
            ah[4][u] = __hadd2(ah[4][u], __habs2(__hsub2(hW0[u], hR[u])));
            ah[3][u] = __hadd2(ah[3][u], __habs2(__hsub2(hW1[u], hR[u])));
            ah[2][u] = __hadd2(ah[2][u], __habs2(__hsub2(hW2[u], hR[u])));
            ah[1][u] = __hadd2(ah[1][u], __habs2(__hsub2(hW3[u], hR[u])));
            ah[0][u] = __hadd2(ah[0][u], __habs2(__hsub2(hW4[u], hR[u])));
        }

        pj += NLANES;
        const bool wrap = (pj >= CROP);
        pj = wrap ? pj - CROP : pj;
        wbase += wrap ? ((NLANES + (EXT - CROP)) * 8) : (NLANES * 8);
        refoff += NLANES * 8;
    }

    // ---- Deterministic block reduction, one round per i1 ----
    __shared__ float sc[8 * NTHR];
    __shared__ float s2[NBT * 24];
    #pragma unroll
    for (int i1 = 0; i1 < 5; i1++) {
        __syncthreads();
        #pragma unroll
        for (int u = 0; u < 4; u++) {
            const float2 df = __half22float2(ah[i1][u]);
            sc[(2 * u)     * NTHR + t] = df.x;
            sc[(2 * u + 1) * NTHR + t] = df.y;
        }
        __syncthreads();
        {
            const int bt = t / 24;
            const int ii = t % 24;
            const int c  = bt * 3 + ii / 8;
            const int gs = c / 8;
            const int k  = c % 8;
            const int m8 = ii % 8;
            float ssum = 0.0f;
            #pragma unroll
            for (int jj = 0; jj < 8; jj++) {
                const int q  = m8 * 8 + jj;
                const int tp = gs * 32 + q + ((q >= 32) ? 64 : 0);
                ssum += sc[k * NTHR + tp];
            }
            s2[bt * 24 + ii] = ssum;
        }
        __syncthreads();
        if (t < NBT) {
            float ssum = 0.0f;
            #pragma unroll
            for (int ii = 0; ii < 24; ii++)
                ssum += s2[t * 24 + ii];
            const int n = i0 * 15 + i1 * 3 + i2;
            g_partial[(n * SPLIT2 + s) * NBT + t] = ssum;
        }
    }

    // ---- Fused finalize ----
    __shared__ int isLast;
    __threadfence();
    __syncthreads();
    if (t == 0) {
        const int old = atomicAdd(&g_count, 1);
        isLast = (old == 15 * SPLIT2 - 1) ? 1 : 0;
    }
    __syncthreads();
    if (isLast) {
        __shared__ float sadSh[NCAND * NBT];
        for (int idx = t; idx < NCAND * NBT; idx += NTHR) {
            const int nn = idx / NBT;
            const int bt = idx - nn * NBT;
            float ssum = 0.0f;
            #pragma unroll
            for (int k = 0; k < SPLIT2; k++)
                ssum += __ldcg(&g_partial[(nn * SPLIT2 + k) * NBT + bt]);
            ssum *= (1.0f / (float)(3 * NPIX));
            sadSh[idx] = ssum;
            out[idx] = ssum;
        }
        __syncthreads();
        if (t < NBT && out_size >= NCAND * NBT + 4 * NBT) {
            const int bt = t;
            float best = sadSh[bt];
            int bn = 0;
            for (int nn = 1; nn < NCAND; nn++) {
                const float v = sadSh[nn * NBT + bt];
                if (v < best) { best = v; bn = nn; }
            }
            const int a0 = bn / 15;
            const int a1 = (bn / 3) % 5;
            const int a2 = bn % 3;
            out[NCAND * NBT + 0 * NBT + bt] = (float)a0;
            out[NCAND * NBT + 1 * NBT + bt] = (float)a1;
            out[NCAND * NBT + 2 * NBT + bt] = (float)a2;
            out[NCAND * NBT + 3 * NBT + bt] = 0.0f;
        }
    }
}

extern "C" void kernel_launch(void* const* d_in, const int* in_sizes, int n_in,
                              void* d_out, int out_size) {
    const float* matrix = (const float*)d_in[0];
    const float* refm   = (const float*)d_in[1];

    prep_kernel<<<3 * NSPLITA + REF_BLKS, NTHR>>>(matrix, refm);

    dim3 gridB(15, SPLIT2);
    sad_kernel<<<gridB, NTHR>>>((float*)d_out, out_size);
}